// round 7
// baseline (speedup 1.0000x reference)
#include <cuda_runtime.h>

// Problem constants
#define BP   128          // B*P
#define SEQ  1024         // S
#define DIM  1024         // D
#define NH   16           // heads
#define DH   64           // depth per head
#define SCALE 0.125f      // 1/sqrt(64)
#define SIGMA 0.1f

// ---------------- scratch (device globals; no allocation allowed) ------------
__device__ float g_qp[BP * DIM];
__device__ float g_kp[BP * DIM];
__device__ float g_vp[BP * DIM];
__device__ float g_part[32 * BP * DIM];   // per-s-chunk partial sums of attn·V
__device__ float g_zh[BP * DIM];          // merged attention output (mean_z)

// ---------------- projection GEMM (software-pipelined) -----------------------
// out[m][n] = x[m][:]·W[:][n] + b[n] + SIGMA*nz[m][n]
// Block: 128 rows x 16 cols, 256 threads, micro-tile 2x4, double-buffered smem.
__device__ __forceinline__ void proj_body(const float* __restrict__ x,
                                          const float* __restrict__ W,
                                          const float* __restrict__ bias,
                                          const float* __restrict__ nz,
                                          float* __restrict__ out,
                                          int colBase)
{
    __shared__ float xs[2][32][132];   // [buf][k][m], padded
    __shared__ float ws[2][32][16];    // [buf][k][n]

    const int tid = threadIdx.x;          // 0..255
    const int tx  = tid & 3;              // 4 col-groups of 4
    const int ty  = tid >> 2;             // 64 row-groups of 2

    // per-thread load coordinates (x tile: 4 float4; W tile: 1 float4 if tid<128)
    int xm[4], xk[4];
#pragma unroll
    for (int r = 0; r < 4; r++) {
        int i = tid + r * 256;
        xm[r] = i >> 3;
        xk[r] = (i & 7) << 2;
    }
    const int wk = tid >> 2;
    const int wn = (tid & 3) << 2;

    float4 xr[4];
    float4 wr = make_float4(0.f, 0.f, 0.f, 0.f);

    // prologue: load + store chunk 0
#pragma unroll
    for (int r = 0; r < 4; r++)
        xr[r] = *reinterpret_cast<const float4*>(x + xm[r] * DIM + xk[r]);
    if (tid < 128)
        wr = *reinterpret_cast<const float4*>(W + wk * DIM + colBase + wn);
#pragma unroll
    for (int r = 0; r < 4; r++) {
        xs[0][xk[r] + 0][xm[r]] = xr[r].x;
        xs[0][xk[r] + 1][xm[r]] = xr[r].y;
        xs[0][xk[r] + 2][xm[r]] = xr[r].z;
        xs[0][xk[r] + 3][xm[r]] = xr[r].w;
    }
    if (tid < 128)
        *reinterpret_cast<float4*>(&ws[0][wk][wn]) = wr;
    __syncthreads();

    float acc[2][4];
#pragma unroll
    for (int i = 0; i < 2; i++)
#pragma unroll
        for (int j = 0; j < 4; j++) acc[i][j] = 0.f;

    for (int c = 0; c < 32; c++) {
        const int buf = c & 1;
        // issue next chunk's global loads (latency overlaps the FMA loop below)
        if (c + 1 < 32) {
            const int kk = (c + 1) * 32;
#pragma unroll
            for (int r = 0; r < 4; r++)
                xr[r] = *reinterpret_cast<const float4*>(x + xm[r] * DIM + kk + xk[r]);
            if (tid < 128)
                wr = *reinterpret_cast<const float4*>(W + (kk + wk) * DIM + colBase + wn);
        }

#pragma unroll 8
        for (int k = 0; k < 32; k++) {
            float2 a = *reinterpret_cast<const float2*>(&xs[buf][k][ty << 1]);
            float4 b = *reinterpret_cast<const float4*>(&ws[buf][k][tx << 2]);
            acc[0][0] += a.x * b.x; acc[0][1] += a.x * b.y;
            acc[0][2] += a.x * b.z; acc[0][3] += a.x * b.w;
            acc[1][0] += a.y * b.x; acc[1][1] += a.y * b.y;
            acc[1][2] += a.y * b.z; acc[1][3] += a.y * b.w;
        }

        if (c + 1 < 32) {
            const int nb = buf ^ 1;
#pragma unroll
            for (int r = 0; r < 4; r++) {
                xs[nb][xk[r] + 0][xm[r]] = xr[r].x;
                xs[nb][xk[r] + 1][xm[r]] = xr[r].y;
                xs[nb][xk[r] + 2][xm[r]] = xr[r].z;
                xs[nb][xk[r] + 3][xm[r]] = xr[r].w;
            }
            if (tid < 128)
                *reinterpret_cast<float4*>(&ws[nb][wk][wn]) = wr;
            __syncthreads();
        }
    }

    int n0 = colBase + (tx << 2);
    float4 bb = *reinterpret_cast<const float4*>(bias + n0);
#pragma unroll
    for (int i = 0; i < 2; i++) {
        int m = (ty << 1) + i;
        float4 nn = *reinterpret_cast<const float4*>(nz + m * DIM + n0);
        float4 r;
        r.x = acc[i][0] + bb.x + SIGMA * nn.x;
        r.y = acc[i][1] + bb.y + SIGMA * nn.y;
        r.z = acc[i][2] + bb.z + SIGMA * nn.z;
        r.w = acc[i][3] + bb.w + SIGMA * nn.w;
        *reinterpret_cast<float4*>(out + m * DIM + n0) = r;
    }
}

__global__ void __launch_bounds__(256)
proj3_kernel(const float* __restrict__ q, const float* __restrict__ k,
             const float* __restrict__ v,
             const float* __restrict__ Wq, const float* __restrict__ Wk,
             const float* __restrict__ Wv,
             const float* __restrict__ bq, const float* __restrict__ bk,
             const float* __restrict__ bv,
             const float* __restrict__ nq, const float* __restrict__ nk,
             const float* __restrict__ nv)
{
    int mat = blockIdx.y;
    const float* x = (mat == 0) ? q  : (mat == 1) ? k  : v;
    const float* W = (mat == 0) ? Wq : (mat == 1) ? Wk : Wv;
    const float* b = (mat == 0) ? bq : (mat == 1) ? bk : bv;
    const float* n = (mat == 0) ? nq : (mat == 1) ? nk : nv;
    float* o       = (mat == 0) ? g_qp : (mat == 1) ? g_kp : g_vp;
    proj_body(x, W, b, n, o, blockIdx.x * 16);
}

__global__ void __launch_bounds__(256)
projZ_kernel(const float* __restrict__ Wz, const float* __restrict__ bz,
             const float* __restrict__ nz, float* __restrict__ z_out)
{
    proj_body(g_zh, Wz, bz, nz, z_out, blockIdx.x * 16);
}

// ---------------- copy K -> K_out (with slot write) + logits ----------------
// (R1/R5 form — verbatim: 82% DRAM measured; do not touch)
__global__ void __launch_bounds__(256)
copyK_kernel(const float* __restrict__ K, float* __restrict__ Kout,
             float* __restrict__ logits, const int* __restrict__ tptr)
{
    const int bp  = blockIdx.y;
    const int s0  = blockIdx.x * 32;
    const int tid = threadIdx.x;
    const int t   = *tptr;

    __shared__ float pds[32][256];   // per-s, per-thread partial dot

    float4 q4 = *reinterpret_cast<const float4*>(g_qp + bp * DIM + (tid << 2));
    const float* kprow = g_kp + bp * DIM;
    const float* Kb = K    + (size_t)bp * SEQ * DIM;
    float*       Ob = Kout + (size_t)bp * SEQ * DIM;

#pragma unroll 4
    for (int sl = 0; sl < 32; sl++) {
        int s = s0 + sl;
        const float* src = (s == t) ? kprow : (Kb + (size_t)s * DIM);
        float4 v = *reinterpret_cast<const float4*>(src + (tid << 2));
        *reinterpret_cast<float4*>(Ob + (size_t)s * DIM + (tid << 2)) = v;
        pds[sl][tid] = v.x * q4.x + v.y * q4.y + v.z * q4.z + v.w * q4.w;
    }
    __syncthreads();

    for (int i = tid; i < 512; i += 256) {
        int h  = i & 15;
        int sl = i >> 4;
        float sum = 0.f;
#pragma unroll
        for (int j = 0; j < 16; j++) sum += pds[sl][(h << 4) + j];
        logits[((size_t)(bp * NH + h)) * SEQ + s0 + sl] = sum * SCALE;
    }
}

// ---------------- softmax in place over attn region (rows of 1024) ----------
__global__ void __launch_bounds__(256)
softmax_kernel(float* __restrict__ attn)
{
    int row  = blockIdx.x * 8 + (threadIdx.x >> 5);   // 2048 rows
    int lane = threadIdx.x & 31;
    float* p = attn + (size_t)row * SEQ;

    float v[32];
    float m = -1e30f;
#pragma unroll
    for (int i = 0; i < 32; i++) { v[i] = p[lane + (i << 5)]; m = fmaxf(m, v[i]); }
#pragma unroll
    for (int o = 16; o > 0; o >>= 1) m = fmaxf(m, __shfl_xor_sync(0xffffffffu, m, o));
    float sum = 0.f;
#pragma unroll
    for (int i = 0; i < 32; i++) { v[i] = __expf(v[i] - m); sum += v[i]; }
#pragma unroll
    for (int o = 16; o > 0; o >>= 1) sum += __shfl_xor_sync(0xffffffffu, sum, o);
    float inv = 1.f / sum;
#pragma unroll
    for (int i = 0; i < 32; i++) p[lane + (i << 5)] = v[i] * inv;
}

// ---------------- copy V -> V_out (slot write) + attn-weighted partials -----
// (R1/R5 form — verbatim)
__global__ void __launch_bounds__(256)
copyV_kernel(const float* __restrict__ V, float* __restrict__ Vout,
             const float* __restrict__ attn, const int* __restrict__ tptr)
{
    const int bp  = blockIdx.y;
    const int s0  = blockIdx.x * 32;
    const int tid = threadIdx.x;
    const int t   = *tptr;

    __shared__ float as[NH][32];
    for (int i = tid; i < NH * 32; i += 256) {
        int h  = i >> 5;
        int sl = i & 31;
        as[h][sl] = attn[((size_t)(bp * NH + h)) * SEQ + s0 + sl];
    }
    __syncthreads();

    const float* vprow = g_vp + bp * DIM;
    const float* Vb = V    + (size_t)bp * SEQ * DIM;
    float*       Ob = Vout + (size_t)bp * SEQ * DIM;

    const int h = tid >> 4;   // head of cols 4t..4t+3
    float4 acc = make_float4(0.f, 0.f, 0.f, 0.f);

#pragma unroll 4
    for (int sl = 0; sl < 32; sl++) {
        int s = s0 + sl;
        const float* src = (s == t) ? vprow : (Vb + (size_t)s * DIM);
        float4 v = *reinterpret_cast<const float4*>(src + (tid << 2));
        *reinterpret_cast<float4*>(Ob + (size_t)s * DIM + (tid << 2)) = v;
        float a = as[h][sl];
        acc.x += a * v.x; acc.y += a * v.y; acc.z += a * v.z; acc.w += a * v.w;
    }
    *reinterpret_cast<float4*>(g_part + ((size_t)blockIdx.x * BP + bp) * DIM + (tid << 2)) = acc;
}

// ---------------- reduce the 32 s-chunk partials into g_zh ------------------
__global__ void __launch_bounds__(256)
reduce_kernel()
{
    int i = blockIdx.x * 256 + threadIdx.x;   // over BP*DIM = 131072
    float s = 0.f;
#pragma unroll
    for (int c = 0; c < 32; c++) s += g_part[c * (BP * DIM) + i];
    g_zh[i] = s;
}

// ---------------- launch ----------------------------------------------------
extern "C" void kernel_launch(void* const* d_in, const int* in_sizes, int n_in,
                              void* d_out, int out_size)
{
    const float* q   = (const float*)d_in[0];
    const float* k   = (const float*)d_in[1];
    const float* v   = (const float*)d_in[2];
    const float* Kin = (const float*)d_in[3];
    const float* Vin = (const float*)d_in[4];
    const float* Wq  = (const float*)d_in[5];
    const float* bq  = (const float*)d_in[6];
    const float* Wk  = (const float*)d_in[7];
    const float* bk  = (const float*)d_in[8];
    const float* Wv  = (const float*)d_in[9];
    const float* bv  = (const float*)d_in[10];
    const float* Wz  = (const float*)d_in[11];
    const float* bz  = (const float*)d_in[12];
    const float* nq  = (const float*)d_in[13];
    const float* nk  = (const float*)d_in[14];
    const float* nv  = (const float*)d_in[15];
    const float* nz  = (const float*)d_in[16];
    const int* tstep = (const int*)d_in[17];

    float* out   = (float*)d_out;
    float* z_out = out;                                       // 128*1024
    float* K_out = out + (size_t)BP * DIM;                    // 128*1024*1024
    float* V_out = K_out + (size_t)BP * SEQ * DIM;
    float* attn  = V_out + (size_t)BP * SEQ * DIM;            // 128*16*1024

    // 1. projections q/k/v (+bias +sigma*noise) — pipelined GEMM
    proj3_kernel<<<dim3(64, 3), 256>>>(q, k, v, Wq, Wk, Wv, bq, bk, bv, nq, nk, nv);
    // 2. K copy (slot write at t) fused with logits
    copyK_kernel<<<dim3(32, BP), 256>>>(Kin, K_out, attn, tstep);
    // 3. softmax in place
    softmax_kernel<<<256, 256>>>(attn);
    // 4. V copy (slot write at t) fused with attn-weighted partial sums
    copyV_kernel<<<dim3(32, BP), 256>>>(Vin, V_out, attn, tstep);
    // 5. reduce partials -> zh
    reduce_kernel<<<512, 256>>>();
    // 6. output projection z
    projZ_kernel<<<dim3(64, 1), 256>>>(Wz, bz, nz, z_out);
}

// round 8
// speedup vs baseline: 1.2535x; 1.2535x over previous
#include <cuda_runtime.h>

// Problem constants
#define BP   128          // B*P
#define SEQ  1024         // S
#define DIM  1024         // D
#define NH   16           // heads
#define DH   64           // depth per head
#define SCALE 0.125f      // 1/sqrt(64)
#define SIGMA 0.1f

// ---------------- scratch (device globals; no allocation allowed) ------------
__device__ float g_qp[BP * DIM];
__device__ float g_kp[BP * DIM];
__device__ float g_vp[BP * DIM];
__device__ float g_part[32 * BP * DIM];    // per-s-chunk partial sums of attn·V
__device__ float g_zh[BP * DIM];           // merged attention output (mean_z)
__device__ float g_p3[6][BP * DIM];        // q/k/v GEMM k-split partials (2 each)
__device__ float g_pz[4][BP * DIM];        // z GEMM k-split partials

// ---------------- partial projection GEMM (R5 body, k-ranged) ----------------
// partial[m][n] = sum_{k in [kBase, kBase+kLen)} x[m][k] * W[k][n]
// Block: 128 rows x 16 cols, 256 threads, micro-tile 2x4.
__device__ __forceinline__ void proj_partial_body(const float* __restrict__ x,
                                                  const float* __restrict__ W,
                                                  float* __restrict__ partial,
                                                  int colBase, int kBase, int kLen)
{
    __shared__ float xs[32][132];   // [k][m], padded
    __shared__ float ws[32][16];    // [k][n]

    const int tid = threadIdx.x;          // 0..255
    const int tx  = tid & 3;              // 4 col-groups of 4
    const int ty  = tid >> 2;             // 64 row-groups of 2

    float acc[2][4];
#pragma unroll
    for (int i = 0; i < 2; i++)
#pragma unroll
        for (int j = 0; j < 4; j++) acc[i][j] = 0.f;

    for (int kk = kBase; kk < kBase + kLen; kk += 32) {
        // x tile: 128 rows x 32 k = 1024 float4 / 256 threads = 4 each
#pragma unroll
        for (int r = 0; r < 4; r++) {
            int i  = tid + r * 256;
            int m  = i >> 3;
            int kq = (i & 7) << 2;
            float4 v = *reinterpret_cast<const float4*>(x + m * DIM + kk + kq);
            xs[kq + 0][m] = v.x;
            xs[kq + 1][m] = v.y;
            xs[kq + 2][m] = v.z;
            xs[kq + 3][m] = v.w;
        }
        // W tile: 32 k x 16 n = 128 float4; threads < 128
        if (tid < 128) {
            int k  = tid >> 2;
            int nq = (tid & 3) << 2;
            *reinterpret_cast<float4*>(&ws[k][nq]) =
                *reinterpret_cast<const float4*>(W + (kk + k) * DIM + colBase + nq);
        }
        __syncthreads();

#pragma unroll 8
        for (int k = 0; k < 32; k++) {
            float2 a = *reinterpret_cast<const float2*>(&xs[k][ty << 1]);
            float4 b = *reinterpret_cast<const float4*>(&ws[k][tx << 2]);
            acc[0][0] += a.x * b.x; acc[0][1] += a.x * b.y;
            acc[0][2] += a.x * b.z; acc[0][3] += a.x * b.w;
            acc[1][0] += a.y * b.x; acc[1][1] += a.y * b.y;
            acc[1][2] += a.y * b.z; acc[1][3] += a.y * b.w;
        }
        __syncthreads();
    }

    int n0 = colBase + (tx << 2);
#pragma unroll
    for (int i = 0; i < 2; i++) {
        int m = (ty << 1) + i;
        float4 r;
        r.x = acc[i][0]; r.y = acc[i][1]; r.z = acc[i][2]; r.w = acc[i][3];
        *reinterpret_cast<float4*>(partial + m * DIM + n0) = r;
    }
}

// proj3: grid (64 col-tiles, 3 matrices, 2 k-halves)
__global__ void __launch_bounds__(256)
proj3_kernel(const float* __restrict__ q, const float* __restrict__ k,
             const float* __restrict__ v,
             const float* __restrict__ Wq, const float* __restrict__ Wk,
             const float* __restrict__ Wv)
{
    const int mat  = blockIdx.y;
    const int half = blockIdx.z;
    const float* x = (mat == 0) ? q  : (mat == 1) ? k  : v;
    const float* W = (mat == 0) ? Wq : (mat == 1) ? Wk : Wv;
    proj_partial_body(x, W, g_p3[mat * 2 + half],
                      blockIdx.x * 16, half * 512, 512);
}

// combine q/k/v partials + bias + sigma*noise -> g_qp/g_kp/g_vp
__global__ void __launch_bounds__(256)
combine3_kernel(const float* __restrict__ bq, const float* __restrict__ bk,
                const float* __restrict__ bv,
                const float* __restrict__ nq, const float* __restrict__ nk,
                const float* __restrict__ nv)
{
    const int mat = blockIdx.y;
    const float* b = (mat == 0) ? bq : (mat == 1) ? bk : bv;
    const float* n = (mat == 0) ? nq : (mat == 1) ? nk : nv;
    float* o       = (mat == 0) ? g_qp : (mat == 1) ? g_kp : g_vp;

    int i = (blockIdx.x * 256 + threadIdx.x) << 2;   // 128 blocks * 256 * 4 = 128K
    float4 p0 = *reinterpret_cast<const float4*>(&g_p3[mat * 2 + 0][i]);
    float4 p1 = *reinterpret_cast<const float4*>(&g_p3[mat * 2 + 1][i]);
    float4 bb = *reinterpret_cast<const float4*>(b + (i & (DIM - 1)));
    float4 nn = *reinterpret_cast<const float4*>(n + i);
    float4 r;
    r.x = p0.x + p1.x + bb.x + SIGMA * nn.x;
    r.y = p0.y + p1.y + bb.y + SIGMA * nn.y;
    r.z = p0.z + p1.z + bb.z + SIGMA * nn.z;
    r.w = p0.w + p1.w + bb.w + SIGMA * nn.w;
    *reinterpret_cast<float4*>(o + i) = r;
}

// projZ: grid (64 col-tiles, 1, 4 k-quarters)
__global__ void __launch_bounds__(256)
projZ_kernel(const float* __restrict__ Wz)
{
    const int quart = blockIdx.z;
    proj_partial_body(g_zh, Wz, g_pz[quart], blockIdx.x * 16, quart * 256, 256);
}

__global__ void __launch_bounds__(256)
combineZ_kernel(const float* __restrict__ bz, const float* __restrict__ nz,
                float* __restrict__ z_out)
{
    int i = (blockIdx.x * 256 + threadIdx.x) << 2;   // 128 blocks
    float4 p0 = *reinterpret_cast<const float4*>(&g_pz[0][i]);
    float4 p1 = *reinterpret_cast<const float4*>(&g_pz[1][i]);
    float4 p2 = *reinterpret_cast<const float4*>(&g_pz[2][i]);
    float4 p3 = *reinterpret_cast<const float4*>(&g_pz[3][i]);
    float4 bb = *reinterpret_cast<const float4*>(bz + (i & (DIM - 1)));
    float4 nn = *reinterpret_cast<const float4*>(nz + i);
    float4 r;
    r.x = ((p0.x + p1.x) + (p2.x + p3.x)) + bb.x + SIGMA * nn.x;
    r.y = ((p0.y + p1.y) + (p2.y + p3.y)) + bb.y + SIGMA * nn.y;
    r.z = ((p0.z + p1.z) + (p2.z + p3.z)) + bb.z + SIGMA * nn.z;
    r.w = ((p0.w + p1.w) + (p2.w + p3.w)) + bb.w + SIGMA * nn.w;
    *reinterpret_cast<float4*>(z_out + i) = r;
}

// ---------------- copy K -> K_out (with slot write) + logits ----------------
// (R1/R5 form — verbatim: 82% DRAM measured; do not touch)
__global__ void __launch_bounds__(256)
copyK_kernel(const float* __restrict__ K, float* __restrict__ Kout,
             float* __restrict__ logits, const int* __restrict__ tptr)
{
    const int bp  = blockIdx.y;
    const int s0  = blockIdx.x * 32;
    const int tid = threadIdx.x;
    const int t   = *tptr;

    __shared__ float pds[32][256];   // per-s, per-thread partial dot

    float4 q4 = *reinterpret_cast<const float4*>(g_qp + bp * DIM + (tid << 2));
    const float* kprow = g_kp + bp * DIM;
    const float* Kb = K    + (size_t)bp * SEQ * DIM;
    float*       Ob = Kout + (size_t)bp * SEQ * DIM;

#pragma unroll 4
    for (int sl = 0; sl < 32; sl++) {
        int s = s0 + sl;
        const float* src = (s == t) ? kprow : (Kb + (size_t)s * DIM);
        float4 v = *reinterpret_cast<const float4*>(src + (tid << 2));
        *reinterpret_cast<float4*>(Ob + (size_t)s * DIM + (tid << 2)) = v;
        pds[sl][tid] = v.x * q4.x + v.y * q4.y + v.z * q4.z + v.w * q4.w;
    }
    __syncthreads();

    for (int i = tid; i < 512; i += 256) {
        int h  = i & 15;
        int sl = i >> 4;
        float sum = 0.f;
#pragma unroll
        for (int j = 0; j < 16; j++) sum += pds[sl][(h << 4) + j];
        logits[((size_t)(bp * NH + h)) * SEQ + s0 + sl] = sum * SCALE;
    }
}

// ---------------- softmax in place over attn region (rows of 1024) ----------
__global__ void __launch_bounds__(256)
softmax_kernel(float* __restrict__ attn)
{
    int row  = blockIdx.x * 8 + (threadIdx.x >> 5);   // 2048 rows
    int lane = threadIdx.x & 31;
    float* p = attn + (size_t)row * SEQ;

    float v[32];
    float m = -1e30f;
#pragma unroll
    for (int i = 0; i < 32; i++) { v[i] = p[lane + (i << 5)]; m = fmaxf(m, v[i]); }
#pragma unroll
    for (int o = 16; o > 0; o >>= 1) m = fmaxf(m, __shfl_xor_sync(0xffffffffu, m, o));
    float sum = 0.f;
#pragma unroll
    for (int i = 0; i < 32; i++) { v[i] = __expf(v[i] - m); sum += v[i]; }
#pragma unroll
    for (int o = 16; o > 0; o >>= 1) sum += __shfl_xor_sync(0xffffffffu, sum, o);
    float inv = 1.f / sum;
#pragma unroll
    for (int i = 0; i < 32; i++) p[lane + (i << 5)] = v[i] * inv;
}

// ---------------- copy V -> V_out (slot write) + attn-weighted partials -----
// (R1/R5 form — verbatim)
__global__ void __launch_bounds__(256)
copyV_kernel(const float* __restrict__ V, float* __restrict__ Vout,
             const float* __restrict__ attn, const int* __restrict__ tptr)
{
    const int bp  = blockIdx.y;
    const int s0  = blockIdx.x * 32;
    const int tid = threadIdx.x;
    const int t   = *tptr;

    __shared__ float as[NH][32];
    for (int i = tid; i < NH * 32; i += 256) {
        int h  = i >> 5;
        int sl = i & 31;
        as[h][sl] = attn[((size_t)(bp * NH + h)) * SEQ + s0 + sl];
    }
    __syncthreads();

    const float* vprow = g_vp + bp * DIM;
    const float* Vb = V    + (size_t)bp * SEQ * DIM;
    float*       Ob = Vout + (size_t)bp * SEQ * DIM;

    const int h = tid >> 4;   // head of cols 4t..4t+3
    float4 acc = make_float4(0.f, 0.f, 0.f, 0.f);

#pragma unroll 4
    for (int sl = 0; sl < 32; sl++) {
        int s = s0 + sl;
        const float* src = (s == t) ? vprow : (Vb + (size_t)s * DIM);
        float4 v = *reinterpret_cast<const float4*>(src + (tid << 2));
        *reinterpret_cast<float4*>(Ob + (size_t)s * DIM + (tid << 2)) = v;
        float a = as[h][sl];
        acc.x += a * v.x; acc.y += a * v.y; acc.z += a * v.z; acc.w += a * v.w;
    }
    *reinterpret_cast<float4*>(g_part + ((size_t)blockIdx.x * BP + bp) * DIM + (tid << 2)) = acc;
}

// ---------------- reduce the 32 s-chunk partials into g_zh ------------------
__global__ void __launch_bounds__(256)
reduce_kernel()
{
    int i = blockIdx.x * 256 + threadIdx.x;   // over BP*DIM = 131072
    float s = 0.f;
#pragma unroll
    for (int c = 0; c < 32; c++) s += g_part[c * (BP * DIM) + i];
    g_zh[i] = s;
}

// ---------------- launch ----------------------------------------------------
extern "C" void kernel_launch(void* const* d_in, const int* in_sizes, int n_in,
                              void* d_out, int out_size)
{
    const float* q   = (const float*)d_in[0];
    const float* k   = (const float*)d_in[1];
    const float* v   = (const float*)d_in[2];
    const float* Kin = (const float*)d_in[3];
    const float* Vin = (const float*)d_in[4];
    const float* Wq  = (const float*)d_in[5];
    const float* bq  = (const float*)d_in[6];
    const float* Wk  = (const float*)d_in[7];
    const float* bk  = (const float*)d_in[8];
    const float* Wv  = (const float*)d_in[9];
    const float* bv  = (const float*)d_in[10];
    const float* Wz  = (const float*)d_in[11];
    const float* bz  = (const float*)d_in[12];
    const float* nq  = (const float*)d_in[13];
    const float* nk  = (const float*)d_in[14];
    const float* nv  = (const float*)d_in[15];
    const float* nz  = (const float*)d_in[16];
    const int* tstep = (const int*)d_in[17];

    float* out   = (float*)d_out;
    float* z_out = out;                                       // 128*1024
    float* K_out = out + (size_t)BP * DIM;                    // 128*1024*1024
    float* V_out = K_out + (size_t)BP * SEQ * DIM;
    float* attn  = V_out + (size_t)BP * SEQ * DIM;            // 128*16*1024

    // 1. q/k/v projection partials (k-split x2) + combine (+bias +sigma*noise)
    proj3_kernel<<<dim3(64, 3, 2), 256>>>(q, k, v, Wq, Wk, Wv);
    combine3_kernel<<<dim3(128, 3), 256>>>(bq, bk, bv, nq, nk, nv);
    // 2. K copy (slot write at t) fused with logits
    copyK_kernel<<<dim3(32, BP), 256>>>(Kin, K_out, attn, tstep);
    // 3. softmax in place
    softmax_kernel<<<256, 256>>>(attn);
    // 4. V copy (slot write at t) fused with attn-weighted partial sums
    copyV_kernel<<<dim3(32, BP), 256>>>(Vin, V_out, attn, tstep);
    // 5. reduce partials -> zh
    reduce_kernel<<<512, 256>>>();
    // 6. z projection partials (k-split x4) + combine
    projZ_kernel<<<dim3(64, 1, 4), 256>>>(Wz);
    combineZ_kernel<<<128, 256>>>(bz, nz, z_out);
}

// round 9
// speedup vs baseline: 1.2718x; 1.0146x over previous
#include <cuda_runtime.h>

// Problem constants
#define BP   128          // B*P
#define SEQ  1024         // S
#define DIM  1024         // D
#define NH   16           // heads
#define DH   64           // depth per head
#define SCALE 0.125f      // 1/sqrt(64)
#define SIGMA 0.1f

// ---------------- scratch (device globals; no allocation allowed) ------------
__device__ float g_qp[BP * DIM];
__device__ float g_kp[BP * DIM];
__device__ float g_vp[BP * DIM];
__device__ float g_part[32 * BP * DIM];    // per-s-chunk partial sums of attn·V
__device__ float g_zh[BP * DIM];           // merged attention output (mean_z)
__device__ float g_p3[12][BP * DIM];       // q/k/v GEMM k-split partials (4 each)
__device__ float g_pz[8][BP * DIM];        // z GEMM k-split partials

// ---------------- partial projection GEMM (k-ranged) -------------------------
// partial[m][n] = sum_{k in [kBase, kBase+kLen)} x[m][k] * W[k][n]
// Block: 128 rows x 16 cols, 256 threads, micro-tile 2x4.
__device__ __forceinline__ void proj_partial_body(const float* __restrict__ x,
                                                  const float* __restrict__ W,
                                                  float* __restrict__ partial,
                                                  int colBase, int kBase, int kLen)
{
    __shared__ float xs[32][132];   // [k][m], padded
    __shared__ float ws[32][16];    // [k][n]

    const int tid = threadIdx.x;          // 0..255
    const int tx  = tid & 3;              // 4 col-groups of 4
    const int ty  = tid >> 2;             // 64 row-groups of 2

    float acc[2][4];
#pragma unroll
    for (int i = 0; i < 2; i++)
#pragma unroll
        for (int j = 0; j < 4; j++) acc[i][j] = 0.f;

    for (int kk = kBase; kk < kBase + kLen; kk += 32) {
        // x tile: 128 rows x 32 k = 1024 float4 / 256 threads = 4 each
#pragma unroll
        for (int r = 0; r < 4; r++) {
            int i  = tid + r * 256;
            int m  = i >> 3;
            int kq = (i & 7) << 2;
            float4 v = *reinterpret_cast<const float4*>(x + m * DIM + kk + kq);
            xs[kq + 0][m] = v.x;
            xs[kq + 1][m] = v.y;
            xs[kq + 2][m] = v.z;
            xs[kq + 3][m] = v.w;
        }
        // W tile: 32 k x 16 n = 128 float4; threads < 128
        if (tid < 128) {
            int k  = tid >> 2;
            int nq = (tid & 3) << 2;
            *reinterpret_cast<float4*>(&ws[k][nq]) =
                *reinterpret_cast<const float4*>(W + (kk + k) * DIM + colBase + nq);
        }
        __syncthreads();

#pragma unroll 8
        for (int k = 0; k < 32; k++) {
            float2 a = *reinterpret_cast<const float2*>(&xs[k][ty << 1]);
            float4 b = *reinterpret_cast<const float4*>(&ws[k][tx << 2]);
            acc[0][0] += a.x * b.x; acc[0][1] += a.x * b.y;
            acc[0][2] += a.x * b.z; acc[0][3] += a.x * b.w;
            acc[1][0] += a.y * b.x; acc[1][1] += a.y * b.y;
            acc[1][2] += a.y * b.z; acc[1][3] += a.y * b.w;
        }
        __syncthreads();
    }

    int n0 = colBase + (tx << 2);
#pragma unroll
    for (int i = 0; i < 2; i++) {
        int m = (ty << 1) + i;
        float4 r;
        r.x = acc[i][0]; r.y = acc[i][1]; r.z = acc[i][2]; r.w = acc[i][3];
        *reinterpret_cast<float4*>(partial + m * DIM + n0) = r;
    }
}

// proj3: grid (64 col-tiles, 3 matrices, 4 k-quarters)
__global__ void __launch_bounds__(256)
proj3_kernel(const float* __restrict__ q, const float* __restrict__ k,
             const float* __restrict__ v,
             const float* __restrict__ Wq, const float* __restrict__ Wk,
             const float* __restrict__ Wv)
{
    const int mat = blockIdx.y;
    const int kq  = blockIdx.z;
    const float* x = (mat == 0) ? q  : (mat == 1) ? k  : v;
    const float* W = (mat == 0) ? Wq : (mat == 1) ? Wk : Wv;
    proj_partial_body(x, W, g_p3[mat * 4 + kq],
                      blockIdx.x * 16, kq * 256, 256);
}

// combine q/k/v partials + bias + sigma*noise -> g_qp/g_kp/g_vp
__global__ void __launch_bounds__(256)
combine3_kernel(const float* __restrict__ bq, const float* __restrict__ bk,
                const float* __restrict__ bv,
                const float* __restrict__ nq, const float* __restrict__ nk,
                const float* __restrict__ nv)
{
    const int mat = blockIdx.y;
    const float* b = (mat == 0) ? bq : (mat == 1) ? bk : bv;
    const float* n = (mat == 0) ? nq : (mat == 1) ? nk : nv;
    float* o       = (mat == 0) ? g_qp : (mat == 1) ? g_kp : g_vp;

    int i = (blockIdx.x * 256 + threadIdx.x) << 2;   // 128 blocks * 256 * 4 = 128K
    float4 p0 = *reinterpret_cast<const float4*>(&g_p3[mat * 4 + 0][i]);
    float4 p1 = *reinterpret_cast<const float4*>(&g_p3[mat * 4 + 1][i]);
    float4 p2 = *reinterpret_cast<const float4*>(&g_p3[mat * 4 + 2][i]);
    float4 p3 = *reinterpret_cast<const float4*>(&g_p3[mat * 4 + 3][i]);
    float4 bb = *reinterpret_cast<const float4*>(b + (i & (DIM - 1)));
    float4 nn = *reinterpret_cast<const float4*>(n + i);
    float4 r;
    r.x = ((p0.x + p1.x) + (p2.x + p3.x)) + bb.x + SIGMA * nn.x;
    r.y = ((p0.y + p1.y) + (p2.y + p3.y)) + bb.y + SIGMA * nn.y;
    r.z = ((p0.z + p1.z) + (p2.z + p3.z)) + bb.z + SIGMA * nn.z;
    r.w = ((p0.w + p1.w) + (p2.w + p3.w)) + bb.w + SIGMA * nn.w;
    *reinterpret_cast<float4*>(o + i) = r;
}

// projZ: grid (64 col-tiles, 1, 8 k-eighths)
__global__ void __launch_bounds__(256)
projZ_kernel(const float* __restrict__ Wz)
{
    const int kq = blockIdx.z;
    proj_partial_body(g_zh, Wz, g_pz[kq], blockIdx.x * 16, kq * 128, 128);
}

__global__ void __launch_bounds__(256)
combineZ_kernel(const float* __restrict__ bz, const float* __restrict__ nz,
                float* __restrict__ z_out)
{
    int i = (blockIdx.x * 256 + threadIdx.x) << 2;   // 128 blocks
    float4 s = make_float4(0.f, 0.f, 0.f, 0.f);
#pragma unroll
    for (int c = 0; c < 8; c++) {
        float4 p = *reinterpret_cast<const float4*>(&g_pz[c][i]);
        s.x += p.x; s.y += p.y; s.z += p.z; s.w += p.w;
    }
    float4 bb = *reinterpret_cast<const float4*>(bz + (i & (DIM - 1)));
    float4 nn = *reinterpret_cast<const float4*>(nz + i);
    float4 r;
    r.x = s.x + bb.x + SIGMA * nn.x;
    r.y = s.y + bb.y + SIGMA * nn.y;
    r.z = s.z + bb.z + SIGMA * nn.z;
    r.w = s.w + bb.w + SIGMA * nn.w;
    *reinterpret_cast<float4*>(z_out + i) = r;
}

// ---------------- copy K -> K_out (with slot write) + logits ----------------
// (R1/R5 form — verbatim: 82% DRAM measured; do not touch)
__global__ void __launch_bounds__(256)
copyK_kernel(const float* __restrict__ K, float* __restrict__ Kout,
             float* __restrict__ logits, const int* __restrict__ tptr)
{
    const int bp  = blockIdx.y;
    const int s0  = blockIdx.x * 32;
    const int tid = threadIdx.x;
    const int t   = *tptr;

    __shared__ float pds[32][256];   // per-s, per-thread partial dot

    float4 q4 = *reinterpret_cast<const float4*>(g_qp + bp * DIM + (tid << 2));
    const float* kprow = g_kp + bp * DIM;
    const float* Kb = K    + (size_t)bp * SEQ * DIM;
    float*       Ob = Kout + (size_t)bp * SEQ * DIM;

#pragma unroll 4
    for (int sl = 0; sl < 32; sl++) {
        int s = s0 + sl;
        const float* src = (s == t) ? kprow : (Kb + (size_t)s * DIM);
        float4 v = *reinterpret_cast<const float4*>(src + (tid << 2));
        *reinterpret_cast<float4*>(Ob + (size_t)s * DIM + (tid << 2)) = v;
        pds[sl][tid] = v.x * q4.x + v.y * q4.y + v.z * q4.z + v.w * q4.w;
    }
    __syncthreads();

    for (int i = tid; i < 512; i += 256) {
        int h  = i & 15;
        int sl = i >> 4;
        float sum = 0.f;
#pragma unroll
        for (int j = 0; j < 16; j++) sum += pds[sl][(h << 4) + j];
        logits[((size_t)(bp * NH + h)) * SEQ + s0 + sl] = sum * SCALE;
    }
}

// ---------------- softmax in place over attn region (rows of 1024) ----------
// one warp per row; 512 blocks x 128 threads for higher SM coverage
__global__ void __launch_bounds__(128)
softmax_kernel(float* __restrict__ attn)
{
    int row  = blockIdx.x * 4 + (threadIdx.x >> 5);   // 2048 rows
    int lane = threadIdx.x & 31;
    float* p = attn + (size_t)row * SEQ;

    float v[32];
    float m = -1e30f;
#pragma unroll
    for (int i = 0; i < 32; i++) { v[i] = p[lane + (i << 5)]; m = fmaxf(m, v[i]); }
#pragma unroll
    for (int o = 16; o > 0; o >>= 1) m = fmaxf(m, __shfl_xor_sync(0xffffffffu, m, o));
    float sum = 0.f;
#pragma unroll
    for (int i = 0; i < 32; i++) { v[i] = __expf(v[i] - m); sum += v[i]; }
#pragma unroll
    for (int o = 16; o > 0; o >>= 1) sum += __shfl_xor_sync(0xffffffffu, sum, o);
    float inv = 1.f / sum;
#pragma unroll
    for (int i = 0; i < 32; i++) p[lane + (i << 5)] = v[i] * inv;
}

// ---------------- copy V -> V_out (slot write) + attn-weighted partials -----
// (R1/R5 form — verbatim)
__global__ void __launch_bounds__(256)
copyV_kernel(const float* __restrict__ V, float* __restrict__ Vout,
             const float* __restrict__ attn, const int* __restrict__ tptr)
{
    const int bp  = blockIdx.y;
    const int s0  = blockIdx.x * 32;
    const int tid = threadIdx.x;
    const int t   = *tptr;

    __shared__ float as[NH][32];
    for (int i = tid; i < NH * 32; i += 256) {
        int h  = i >> 5;
        int sl = i & 31;
        as[h][sl] = attn[((size_t)(bp * NH + h)) * SEQ + s0 + sl];
    }
    __syncthreads();

    const float* vprow = g_vp + bp * DIM;
    const float* Vb = V    + (size_t)bp * SEQ * DIM;
    float*       Ob = Vout + (size_t)bp * SEQ * DIM;

    const int h = tid >> 4;   // head of cols 4t..4t+3
    float4 acc = make_float4(0.f, 0.f, 0.f, 0.f);

#pragma unroll 4
    for (int sl = 0; sl < 32; sl++) {
        int s = s0 + sl;
        const float* src = (s == t) ? vprow : (Vb + (size_t)s * DIM);
        float4 v = *reinterpret_cast<const float4*>(src + (tid << 2));
        *reinterpret_cast<float4*>(Ob + (size_t)s * DIM + (tid << 2)) = v;
        float a = as[h][sl];
        acc.x += a * v.x; acc.y += a * v.y; acc.z += a * v.z; acc.w += a * v.w;
    }
    *reinterpret_cast<float4*>(g_part + ((size_t)blockIdx.x * BP + bp) * DIM + (tid << 2)) = acc;
}

// ---------------- reduce the 32 s-chunk partials into g_zh ------------------
__global__ void __launch_bounds__(256)
reduce_kernel()
{
    int i = blockIdx.x * 256 + threadIdx.x;   // over BP*DIM = 131072
    float s = 0.f;
#pragma unroll
    for (int c = 0; c < 32; c++) s += g_part[c * (BP * DIM) + i];
    g_zh[i] = s;
}

// ---------------- launch ----------------------------------------------------
extern "C" void kernel_launch(void* const* d_in, const int* in_sizes, int n_in,
                              void* d_out, int out_size)
{
    const float* q   = (const float*)d_in[0];
    const float* k   = (const float*)d_in[1];
    const float* v   = (const float*)d_in[2];
    const float* Kin = (const float*)d_in[3];
    const float* Vin = (const float*)d_in[4];
    const float* Wq  = (const float*)d_in[5];
    const float* bq  = (const float*)d_in[6];
    const float* Wk  = (const float*)d_in[7];
    const float* bk  = (const float*)d_in[8];
    const float* Wv  = (const float*)d_in[9];
    const float* bv  = (const float*)d_in[10];
    const float* Wz  = (const float*)d_in[11];
    const float* bz  = (const float*)d_in[12];
    const float* nq  = (const float*)d_in[13];
    const float* nk  = (const float*)d_in[14];
    const float* nv  = (const float*)d_in[15];
    const float* nz  = (const float*)d_in[16];
    const int* tstep = (const int*)d_in[17];

    float* out   = (float*)d_out;
    float* z_out = out;                                       // 128*1024
    float* K_out = out + (size_t)BP * DIM;                    // 128*1024*1024
    float* V_out = K_out + (size_t)BP * SEQ * DIM;
    float* attn  = V_out + (size_t)BP * SEQ * DIM;            // 128*16*1024

    // 1. q/k/v projection partials (k-split x4) + combine (+bias +sigma*noise)
    proj3_kernel<<<dim3(64, 3, 4), 256>>>(q, k, v, Wq, Wk, Wv);
    combine3_kernel<<<dim3(128, 3), 256>>>(bq, bk, bv, nq, nk, nv);
    // 2. K copy (slot write at t) fused with logits
    copyK_kernel<<<dim3(32, BP), 256>>>(Kin, K_out, attn, tstep);
    // 3. softmax in place
    softmax_kernel<<<512, 128>>>(attn);
    // 4. V copy (slot write at t) fused with attn-weighted partial sums
    copyV_kernel<<<dim3(32, BP), 256>>>(Vin, V_out, attn, tstep);
    // 5. reduce partials -> zh
    reduce_kernel<<<512, 256>>>();
    // 6. z projection partials (k-split x8) + combine
    projZ_kernel<<<dim3(64, 1, 8), 256>>>(Wz);
    combineZ_kernel<<<128, 256>>>(bz, nz, z_out);
}

// round 12
// speedup vs baseline: 1.3566x; 1.0667x over previous
#include <cuda_runtime.h>

// Problem constants
#define BP   128          // B*P
#define SEQ  1024         // S
#define DIM  1024         // D
#define NH   16           // heads
#define DH   64           // depth per head
#define SCALE 0.125f      // 1/sqrt(64)
#define SIGMA 0.1f

// ---------------- scratch (device globals; no allocation allowed) ------------
__device__ float g_qp[BP * DIM];
__device__ float g_kp[BP * DIM];
__device__ float g_vp[BP * DIM];
__device__ float g_part[32 * BP * DIM];    // per-s-chunk partial sums of attn·V
__device__ float g_zh[BP * DIM];           // merged attention output (mean_z)
__device__ float g_p3[12][BP * DIM];       // q/k/v GEMM k-split partials (4 each)
__device__ float g_pz[8][BP * DIM];        // z GEMM k-split partials

// ---------------- partial projection GEMM (k-ranged, 4x4 micro-tile) --------
// partial[m][n] = sum_{k in [kBase, kBase+kLen)} x[m][k] * W[k][n]
// Block: 128 rows x 32 cols, 256 threads, micro-tile 4x4 (16 FMA per 2 LDS.128).
__device__ __forceinline__ void proj_partial_body(const float* __restrict__ x,
                                                  const float* __restrict__ W,
                                                  float* __restrict__ partial,
                                                  int colBase, int kBase, int kLen)
{
    __shared__ float xs[32][132];   // [k][m], padded
    __shared__ float ws[32][36];    // [k][n], padded

    const int tid = threadIdx.x;          // 0..255
    const int tx  = tid & 7;              // 8 col-groups of 4
    const int ty  = tid >> 3;             // 32 row-groups of 4

    float acc[4][4];
#pragma unroll
    for (int i = 0; i < 4; i++)
#pragma unroll
        for (int j = 0; j < 4; j++) acc[i][j] = 0.f;

    for (int kk = kBase; kk < kBase + kLen; kk += 32) {
        // x tile: 128 rows x 32 k = 1024 float4 / 256 threads = 4 each
#pragma unroll
        for (int r = 0; r < 4; r++) {
            int i  = tid + r * 256;
            int m  = i >> 3;
            int kq = (i & 7) << 2;
            float4 v = *reinterpret_cast<const float4*>(x + m * DIM + kk + kq);
            xs[kq + 0][m] = v.x;
            xs[kq + 1][m] = v.y;
            xs[kq + 2][m] = v.z;
            xs[kq + 3][m] = v.w;
        }
        // W tile: 32 k x 32 n = 256 float4 = 1 per thread
        {
            int k  = tid >> 3;
            int nq = (tid & 7) << 2;
            *reinterpret_cast<float4*>(&ws[k][nq]) =
                *reinterpret_cast<const float4*>(W + (kk + k) * DIM + colBase + nq);
        }
        __syncthreads();

#pragma unroll 8
        for (int k = 0; k < 32; k++) {
            float4 a = *reinterpret_cast<const float4*>(&xs[k][ty << 2]);
            float4 b = *reinterpret_cast<const float4*>(&ws[k][tx << 2]);
            acc[0][0] += a.x * b.x; acc[0][1] += a.x * b.y;
            acc[0][2] += a.x * b.z; acc[0][3] += a.x * b.w;
            acc[1][0] += a.y * b.x; acc[1][1] += a.y * b.y;
            acc[1][2] += a.y * b.z; acc[1][3] += a.y * b.w;
            acc[2][0] += a.z * b.x; acc[2][1] += a.z * b.y;
            acc[2][2] += a.z * b.z; acc[2][3] += a.z * b.w;
            acc[3][0] += a.w * b.x; acc[3][1] += a.w * b.y;
            acc[3][2] += a.w * b.z; acc[3][3] += a.w * b.w;
        }
        __syncthreads();
    }

    int n0 = colBase + (tx << 2);
#pragma unroll
    for (int i = 0; i < 4; i++) {
        int m = (ty << 2) + i;
        float4 r;
        r.x = acc[i][0]; r.y = acc[i][1]; r.z = acc[i][2]; r.w = acc[i][3];
        *reinterpret_cast<float4*>(partial + m * DIM + n0) = r;
    }
}

// proj3: grid (32 col-tiles, 3 matrices, 4 k-quarters)
__global__ void __launch_bounds__(256)
proj3_kernel(const float* __restrict__ q, const float* __restrict__ k,
             const float* __restrict__ v,
             const float* __restrict__ Wq, const float* __restrict__ Wk,
             const float* __restrict__ Wv)
{
    const int mat = blockIdx.y;
    const int kq  = blockIdx.z;
    const float* x = (mat == 0) ? q  : (mat == 1) ? k  : v;
    const float* W = (mat == 0) ? Wq : (mat == 1) ? Wk : Wv;
    proj_partial_body(x, W, g_p3[mat * 4 + kq],
                      blockIdx.x * 32, kq * 256, 256);
}

// combine q/k/v partials + bias + sigma*noise -> g_qp/g_kp/g_vp
__global__ void __launch_bounds__(256)
combine3_kernel(const float* __restrict__ bq, const float* __restrict__ bk,
                const float* __restrict__ bv,
                const float* __restrict__ nq, const float* __restrict__ nk,
                const float* __restrict__ nv)
{
    const int mat = blockIdx.y;
    const float* b = (mat == 0) ? bq : (mat == 1) ? bk : bv;
    const float* n = (mat == 0) ? nq : (mat == 1) ? nk : nv;
    float* o       = (mat == 0) ? g_qp : (mat == 1) ? g_kp : g_vp;

    int i = (blockIdx.x * 256 + threadIdx.x) << 2;   // 128 blocks * 256 * 4 = 128K
    float4 p0 = *reinterpret_cast<const float4*>(&g_p3[mat * 4 + 0][i]);
    float4 p1 = *reinterpret_cast<const float4*>(&g_p3[mat * 4 + 1][i]);
    float4 p2 = *reinterpret_cast<const float4*>(&g_p3[mat * 4 + 2][i]);
    float4 p3 = *reinterpret_cast<const float4*>(&g_p3[mat * 4 + 3][i]);
    float4 bb = *reinterpret_cast<const float4*>(b + (i & (DIM - 1)));
    float4 nn = *reinterpret_cast<const float4*>(n + i);
    float4 r;
    r.x = ((p0.x + p1.x) + (p2.x + p3.x)) + bb.x + SIGMA * nn.x;
    r.y = ((p0.y + p1.y) + (p2.y + p3.y)) + bb.y + SIGMA * nn.y;
    r.z = ((p0.z + p1.z) + (p2.z + p3.z)) + bb.z + SIGMA * nn.z;
    r.w = ((p0.w + p1.w) + (p2.w + p3.w)) + bb.w + SIGMA * nn.w;
    *reinterpret_cast<float4*>(o + i) = r;
}

// projZ: grid (32 col-tiles, 1, 8 k-eighths)
__global__ void __launch_bounds__(256)
projZ_kernel(const float* __restrict__ Wz)
{
    const int kq = blockIdx.z;
    proj_partial_body(g_zh, Wz, g_pz[kq], blockIdx.x * 32, kq * 128, 128);
}

__global__ void __launch_bounds__(256)
combineZ_kernel(const float* __restrict__ bz, const float* __restrict__ nz,
                float* __restrict__ z_out)
{
    int i = (blockIdx.x * 256 + threadIdx.x) << 2;   // 128 blocks
    float4 s = make_float4(0.f, 0.f, 0.f, 0.f);
#pragma unroll
    for (int c = 0; c < 8; c++) {
        float4 p = *reinterpret_cast<const float4*>(&g_pz[c][i]);
        s.x += p.x; s.y += p.y; s.z += p.z; s.w += p.w;
    }
    float4 bb = *reinterpret_cast<const float4*>(bz + (i & (DIM - 1)));
    float4 nn = *reinterpret_cast<const float4*>(nz + i);
    float4 r;
    r.x = s.x + bb.x + SIGMA * nn.x;
    r.y = s.y + bb.y + SIGMA * nn.y;
    r.z = s.z + bb.z + SIGMA * nn.z;
    r.w = s.w + bb.w + SIGMA * nn.w;
    *reinterpret_cast<float4*>(z_out + i) = r;
}

// ---------------- copy K -> K_out (with slot write) + logits ----------------
// (R1/R5 form — verbatim: 82% DRAM measured; do not touch)
__global__ void __launch_bounds__(256)
copyK_kernel(const float* __restrict__ K, float* __restrict__ Kout,
             float* __restrict__ logits, const int* __restrict__ tptr)
{
    const int bp  = blockIdx.y;
    const int s0  = blockIdx.x * 32;
    const int tid = threadIdx.x;
    const int t   = *tptr;

    __shared__ float pds[32][256];   // per-s, per-thread partial dot

    float4 q4 = *reinterpret_cast<const float4*>(g_qp + bp * DIM + (tid << 2));
    const float* kprow = g_kp + bp * DIM;
    const float* Kb = K    + (size_t)bp * SEQ * DIM;
    float*       Ob = Kout + (size_t)bp * SEQ * DIM;

#pragma unroll 4
    for (int sl = 0; sl < 32; sl++) {
        int s = s0 + sl;
        const float* src = (s == t) ? kprow : (Kb + (size_t)s * DIM);
        float4 v = *reinterpret_cast<const float4*>(src + (tid << 2));
        *reinterpret_cast<float4*>(Ob + (size_t)s * DIM + (tid << 2)) = v;
        pds[sl][tid] = v.x * q4.x + v.y * q4.y + v.z * q4.z + v.w * q4.w;
    }
    __syncthreads();

    for (int i = tid; i < 512; i += 256) {
        int h  = i & 15;
        int sl = i >> 4;
        float sum = 0.f;
#pragma unroll
        for (int j = 0; j < 16; j++) sum += pds[sl][(h << 4) + j];
        logits[((size_t)(bp * NH + h)) * SEQ + s0 + sl] = sum * SCALE;
    }
}

// ---------------- softmax in place over attn region (rows of 1024) ----------
// one warp per row; 512 blocks x 128 threads
__global__ void __launch_bounds__(128)
softmax_kernel(float* __restrict__ attn)
{
    int row  = blockIdx.x * 4 + (threadIdx.x >> 5);   // 2048 rows
    int lane = threadIdx.x & 31;
    float* p = attn + (size_t)row * SEQ;

    float v[32];
    float m = -1e30f;
#pragma unroll
    for (int i = 0; i < 32; i++) { v[i] = p[lane + (i << 5)]; m = fmaxf(m, v[i]); }
#pragma unroll
    for (int o = 16; o > 0; o >>= 1) m = fmaxf(m, __shfl_xor_sync(0xffffffffu, m, o));
    float sum = 0.f;
#pragma unroll
    for (int i = 0; i < 32; i++) { v[i] = __expf(v[i] - m); sum += v[i]; }
#pragma unroll
    for (int o = 16; o > 0; o >>= 1) sum += __shfl_xor_sync(0xffffffffu, sum, o);
    float inv = 1.f / sum;
#pragma unroll
    for (int i = 0; i < 32; i++) p[lane + (i << 5)] = v[i] * inv;
}

// ---------------- copy V -> V_out (slot write) + attn-weighted partials -----
// (R1/R5 form — verbatim)
__global__ void __launch_bounds__(256)
copyV_kernel(const float* __restrict__ V, float* __restrict__ Vout,
             const float* __restrict__ attn, const int* __restrict__ tptr)
{
    const int bp  = blockIdx.y;
    const int s0  = blockIdx.x * 32;
    const int tid = threadIdx.x;
    const int t   = *tptr;

    __shared__ float as[NH][32];
    for (int i = tid; i < NH * 32; i += 256) {
        int h  = i >> 5;
        int sl = i & 31;
        as[h][sl] = attn[((size_t)(bp * NH + h)) * SEQ + s0 + sl];
    }
    __syncthreads();

    const float* vprow = g_vp + bp * DIM;
    const float* Vb = V    + (size_t)bp * SEQ * DIM;
    float*       Ob = Vout + (size_t)bp * SEQ * DIM;

    const int h = tid >> 4;   // head of cols 4t..4t+3
    float4 acc = make_float4(0.f, 0.f, 0.f, 0.f);

#pragma unroll 4
    for (int sl = 0; sl < 32; sl++) {
        int s = s0 + sl;
        const float* src = (s == t) ? vprow : (Vb + (size_t)s * DIM);
        float4 v = *reinterpret_cast<const float4*>(src + (tid << 2));
        *reinterpret_cast<float4*>(Ob + (size_t)s * DIM + (tid << 2)) = v;
        float a = as[h][sl];
        acc.x += a * v.x; acc.y += a * v.y; acc.z += a * v.z; acc.w += a * v.w;
    }
    *reinterpret_cast<float4*>(g_part + ((size_t)blockIdx.x * BP + bp) * DIM + (tid << 2)) = acc;
}

// ---------------- reduce the 32 s-chunk partials into g_zh ------------------
__global__ void __launch_bounds__(256)
reduce_kernel()
{
    int i = blockIdx.x * 256 + threadIdx.x;   // over BP*DIM = 131072
    float s = 0.f;
#pragma unroll
    for (int c = 0; c < 32; c++) s += g_part[c * (BP * DIM) + i];
    g_zh[i] = s;
}

// ---------------- launch ----------------------------------------------------
extern "C" void kernel_launch(void* const* d_in, const int* in_sizes, int n_in,
                              void* d_out, int out_size)
{
    const float* q   = (const float*)d_in[0];
    const float* k   = (const float*)d_in[1];
    const float* v   = (const float*)d_in[2];
    const float* Kin = (const float*)d_in[3];
    const float* Vin = (const float*)d_in[4];
    const float* Wq  = (const float*)d_in[5];
    const float* bq  = (const float*)d_in[6];
    const float* Wk  = (const float*)d_in[7];
    const float* bk  = (const float*)d_in[8];
    const float* Wv  = (const float*)d_in[9];
    const float* bv  = (const float*)d_in[10];
    const float* Wz  = (const float*)d_in[11];
    const float* bz  = (const float*)d_in[12];
    const float* nq  = (const float*)d_in[13];
    const float* nk  = (const float*)d_in[14];
    const float* nv  = (const float*)d_in[15];
    const float* nz  = (const float*)d_in[16];
    const int* tstep = (const int*)d_in[17];

    float* out   = (float*)d_out;
    float* z_out = out;                                       // 128*1024
    float* K_out = out + (size_t)BP * DIM;                    // 128*1024*1024
    float* V_out = K_out + (size_t)BP * SEQ * DIM;
    float* attn  = V_out + (size_t)BP * SEQ * DIM;            // 128*16*1024

    // 1. q/k/v projection partials (k-split x4, 4x4 micro-tile) + combine
    proj3_kernel<<<dim3(32, 3, 4), 256>>>(q, k, v, Wq, Wk, Wv);
    combine3_kernel<<<dim3(128, 3), 256>>>(bq, bk, bv, nq, nk, nv);
    // 2. K copy (slot write at t) fused with logits
    copyK_kernel<<<dim3(32, BP), 256>>>(Kin, K_out, attn, tstep);
    // 3. softmax in place
    softmax_kernel<<<512, 128>>>(attn);
    // 4. V copy (slot write at t) fused with attn-weighted partial sums
    copyV_kernel<<<dim3(32, BP), 256>>>(Vin, V_out, attn, tstep);
    // 5. reduce partials -> zh
    reduce_kernel<<<512, 256>>>();
    // 6. z projection partials (k-split x8) + combine
    projZ_kernel<<<dim3(32, 1, 8), 256>>>(Wz);
    combineZ_kernel<<<128, 256>>>(bz, nz, z_out);
}